// round 14
// baseline (speedup 1.0000x reference)
#include <cuda_runtime.h>
#include <cstdint>

#define BATCH 64
#define NTOK  65536            // 256*256
#define KSEL  16384
#define TOTAL (BATCH * NTOK)
#define CANDCAP 4096           // per-batch candidate capacity (global)
#define WCAP    64             // per-warp candidate capacity (expected ~5, huge margin)
#define MCAP    64             // boundary-bin member capacity (expected ~3)

// ---- device scratch (device globals; no allocations) ----
__device__ uint2    g_cand[BATCH * CANDCAP];  // (u bits, delta bits)
__device__ uint32_t g_nc[BATCH];     // candidate counts (zero-init; reset by finalize)
__device__ uint32_t g_c2[BATCH];     // counts >= P2     (zero-init; reset by finalize)
__device__ uint32_t g_of[BATCH];     // overflow flags   (zero-init; reset by finalize)
__device__ uint32_t g_eqcnt[BATCH];  // tie counter (fallback only; reset by finalize)
__device__ double   g_acc;           // loss accumulator
__device__ unsigned g_done;          // finalize ticket

#define P1F 0.73f
#define P2F 0.77f

// ============================================================================
// Kernel 1: THE sweep (80 MB). 4096 blocks x 256 thr x 1 uint4-group (4
// tokens): exactly ONE burst of 5 independent LDG.128 per thread, issued at
// block start -> no serialized load rounds, regs stay low, occupancy high.
// Provisional sel guess: u >= P2 (certain outside window [P1,P2)); window
// tokens stash (u, delta) where delta = min(sp-d,100) - min(sp,100).
// ============================================================================
__global__ __launch_bounds__(256) void sweep_kernel(const float4* __restrict__ zs4,
                                                    const uint4*  __restrict__ sm4,
                                                    const float4* __restrict__ gn4) {
    __shared__ uint2    wbuf[8 * WCAP];
    __shared__ uint32_t wcnt[8];
    __shared__ double   wpart[8];
    __shared__ uint32_t wc2[8];

    const int t    = threadIdx.x;
    const int lane = t & 31;
    const int w    = t >> 5;
    const int b    = blockIdx.x >> 6;               // 64 blocks per batch
    const int g    = blockIdx.x * 256 + t;          // uint4-group index

    if (lane == 0) wcnt[w] = 0u;
    __syncwarp();

    const uint32_t P1 = __float_as_uint(P1F);
    const uint32_t P2 = __float_as_uint(P2F);
    const uint32_t W  = P2 - P1;

    // ---- the single load burst: 5 independent LDG.128 ----
    uint4  u  = sm4[g];
    float4 za = __ldcs(&zs4[2 * g]);
    float4 zb = __ldcs(&zs4[2 * g + 1]);
    float4 ga = __ldcs(&gn4[2 * g]);
    float4 gb = __ldcs(&gn4[2 * g + 1]);

    float d[4];
    d[0] = (za.x + ga.x) - (za.y + ga.y);
    d[1] = (za.z + ga.z) - (za.w + ga.w);
    d[2] = (zb.x + gb.x) - (zb.y + gb.y);
    d[3] = (zb.z + gb.z) - (zb.w + gb.w);

    uint32_t uu[4] = {u.x, u.y, u.z, u.w};

    float facc = 0.0f;
    uint32_t cnt2 = 0;
    #pragma unroll
    for (int k = 0; k < 4; k++) {
        const float dd = d[k];
        const uint32_t uv = uu[k];
        const float c  = __logf(1.0f + __expf(-fabsf(dd)));
        const float sp = c + fmaxf(dd, 0.0f);
        const float t_un = fminf(sp, 100.0f);
        const float t_se = fminf(sp - dd, 100.0f);
        const bool hi = (uv >= P2);
        cnt2 += hi;
        facc += hi ? t_se : t_un;
        if ((uv - P1) < W) {                        // rare (~4%): stash correction
            uint32_t idx = atomicAdd(&wcnt[w], 1u);
            if (idx < WCAP) wbuf[w * WCAP + idx] = make_uint2(uv, __float_as_uint(t_se - t_un));
        }
    }

    double acc = (double)facc;
    #pragma unroll
    for (int off = 16; off > 0; off >>= 1) {
        acc  += __shfl_down_sync(0xFFFFFFFFu, acc,  off);
        cnt2 += __shfl_down_sync(0xFFFFFFFFu, cnt2, off);
    }
    if (lane == 0) { wpart[w] = acc; wc2[w] = cnt2; }
    __syncwarp();

    // per-warp candidate flush (one global atomic per warp)
    uint32_t cw = wcnt[w];
    uint32_t n  = (cw > WCAP) ? WCAP : cw;
    uint32_t gbase = 0;
    if (lane == 0) {
        if (cw > WCAP) g_of[b] = 1u;
        gbase = atomicAdd(&g_nc[b], n);
        if (gbase + n > CANDCAP) g_of[b] = 1u;
    }
    gbase = __shfl_sync(0xFFFFFFFFu, gbase, 0);
    for (uint32_t i = lane; i < n; i += 32)
        if (gbase + i < CANDCAP) g_cand[b * CANDCAP + gbase + i] = wbuf[w * WCAP + i];

    __syncthreads();
    if (t == 0) {
        double bsum = 0.0; uint32_t tot2 = 0;
        #pragma unroll
        for (int i = 0; i < 8; i++) { bsum += wpart[i]; tot2 += wc2[i]; }
        atomicAdd(&g_acc, bsum);
        atomicAdd(&g_c2[b], tot2);
    }
}

// ============================================================================
// Kernel 2: per-batch correction (R10 version, measured-good / invariant).
// Histogram (count + delta-sum) over staged candidates, suffix scan to the
// boundary bin, exact rank select on its ~3 members.
// Miss fallback (never taken): full radix + full re-read. Finalize via ticket.
// ============================================================================
__device__ __forceinline__ uint32_t suffix_excl_512(uint32_t v, uint32_t* wsum) {
    const int t = threadIdx.x, lane = t & 31, w = t >> 5;
    uint32_t s = v;
    #pragma unroll
    for (int off = 1; off < 32; off <<= 1) {
        uint32_t o = __shfl_down_sync(0xFFFFFFFFu, s, off);
        if (lane + off < 32) s += o;
    }
    if (lane == 0) wsum[w] = s;
    __syncthreads();
    if (t < 32) {
        uint32_t x  = (t < 16) ? wsum[t] : 0u;
        uint32_t sx = x;
        #pragma unroll
        for (int off = 1; off < 16; off <<= 1) {
            uint32_t o = __shfl_down_sync(0xFFFFFFFFu, sx, off);
            if (t + off < 16) sx += o;
        }
        if (t < 16) wsum[t] = sx - x;
    }
    __syncthreads();
    return wsum[w] + (s - v);
}

__global__ __launch_bounds__(512) void fix_kernel(const float4* __restrict__ zs4,
                                                  const float*  __restrict__ smap,
                                                  const float4* __restrict__ gn4,
                                                  float* __restrict__ out) {
    __shared__ uint2    scand[CANDCAP];     // 32 KB candidate stage
    __shared__ uint32_t hcnt[1024];
    __shared__ float    hsum[1024];
    __shared__ uint32_t wsum[32];
    __shared__ uint32_t sBin, sK, mcnt;
    __shared__ uint32_t mu[MCAP];
    __shared__ float    md[MCAP];
    __shared__ double   dpart[16];

    const int b = blockIdx.x;
    const int t = threadIdx.x;
    const int lane = t & 31;
    const int w    = t >> 5;
    const uint32_t P1 = __float_as_uint(P1F);
    const uint32_t P2 = __float_as_uint(P2F);

    const uint32_t nc = g_nc[b];
    const uint32_t c2 = g_c2[b];
    bool miss = (g_of[b] != 0u) || (c2 >= KSEL) || (c2 + nc < KSEL) || (nc > CANDCAP);

    const uint2* __restrict__ candg = g_cand + b * CANDCAP;
    const uint32_t* __restrict__ full =
        reinterpret_cast<const uint32_t*>(smap) + (size_t)b * NTOK;

    double corr = 0.0;

    if (!miss) {
        for (uint32_t i = t; i < nc; i += 512) scand[i] = __ldcg(&candg[i]);
        for (int i = t; i < 1024; i += 512) { hcnt[i] = 0u; hsum[i] = 0.0f; }
        if (t == 0) mcnt = 0u;
        __syncthreads();

        for (uint32_t i = t; i < nc; i += 512) {
            uint2 cv = scand[i];
            uint32_t bin = (cv.x - P1) >> 10;       // < 1024
            atomicAdd(&hcnt[bin], 1u);
            atomicAdd(&hsum[bin], __uint_as_float(cv.y));
        }
        __syncthreads();

        const uint32_t Kcur = (uint32_t)KSEL - c2;
        const int base = t * 2;
        uint32_t p = hcnt[base] + hcnt[base + 1];
        uint32_t sfx = suffix_excl_512(p, wsum);
        for (int j = 1; j >= 0; j--) {
            uint32_t h = hcnt[base + j];
            uint32_t s_incl = sfx + h;
            if (sfx < Kcur && s_incl >= Kcur) { sBin = (uint32_t)(base + j); sK = Kcur - sfx; }
            sfx = s_incl;
        }
        __syncthreads();
        const uint32_t bin = sBin;
        const uint32_t rk  = sK;

        float ch = 0.0f;
        for (int i = t; i < 1024; i += 512)
            if ((uint32_t)i > bin) ch += hsum[i];
        corr += (double)ch;

        for (uint32_t i = t; i < nc; i += 512) {
            uint2 cv = scand[i];
            if (((cv.x - P1) >> 10) == bin) {
                uint32_t idx = atomicAdd(&mcnt, 1u);
                if (idx < MCAP) { mu[idx] = cv.x; md[idx] = __uint_as_float(cv.y); }
            }
        }
        __syncthreads();

        if (mcnt <= MCAP) {
            if (w == 0) {
                const uint32_t m = mcnt;
                float csum = 0.0f;
                for (uint32_t e = lane; e < m; e += 32) {
                    uint32_t ue = mu[e];
                    uint32_t rank = 0;
                    for (uint32_t j = 0; j < m; j++) {
                        uint32_t uj = mu[j];
                        rank += (uj > ue) || (uj == ue && j < e);
                    }
                    if (rank < rk) csum += md[e];
                }
                #pragma unroll
                for (int off = 16; off > 0; off >>= 1)
                    csum += __shfl_down_sync(0xFFFFFFFFu, csum, off);
                if (lane == 0) corr += (double)csum;
            }
        } else {
            miss = true;
            corr = 0.0;
        }
        __syncthreads();
    }

    if (miss) {
        uint32_t Kcur = KSEL;
        uint32_t prefixVal = 0;
        for (int r = 0; r < 4; r++) {
            const int shift = 24 - 8 * r;
            if (t < 256) hcnt[t] = 0u;
            __syncthreads();
            for (int i = t; i < NTOK; i += 512) {
                uint32_t u = full[i];
                bool match = (r == 0) || ((u >> (shift + 8)) == prefixVal);
                if (match) atomicAdd(&hcnt[(u >> shift) & 255u], 1u);
            }
            __syncthreads();
            uint32_t p = (t < 256) ? hcnt[t] : 0u;
            uint32_t sfx = suffix_excl_512(p, wsum);
            if (t < 256) {
                uint32_t s_incl = sfx + p;
                if (sfx < Kcur && s_incl >= Kcur) { sBin = (uint32_t)t; sK = Kcur - sfx; }
            }
            __syncthreads();
            prefixVal = (prefixVal << 8) | sBin;
            Kcur = sK;
            __syncthreads();
        }
        const uint32_t T = prefixVal;
        const uint32_t req = sK;

        corr = 0.0;
        const float4* zsb = zs4 + (size_t)b * (NTOK / 2);
        const float4* gnb = gn4 + (size_t)b * (NTOK / 2);
        for (int i = t; i < NTOK / 2; i += 512) {       // 2 tokens per float4
            float4 z = zsb[i], g = gnb[i];
            float dv[2] = {(z.x + g.x) - (z.y + g.y), (z.z + g.z) - (z.w + g.w)};
            #pragma unroll
            for (int c = 0; c < 2; c++) {
                uint32_t u = full[2 * i + c];
                bool assumed = (u >= P2);
                bool truesel;
                if (u > T)       truesel = true;
                else if (u == T) truesel = (atomicAdd(&g_eqcnt[b], 1u) < req);
                else             truesel = false;
                if (truesel != assumed) {
                    float dd = dv[c];
                    float cc = __logf(1.0f + __expf(-fabsf(dd)));
                    float sp = cc + fmaxf(dd, 0.0f);
                    float delta = fminf(sp - dd, 100.0f) - fminf(sp, 100.0f);
                    corr += truesel ? (double)delta : -(double)delta;
                }
            }
        }
    }

    #pragma unroll
    for (int off = 16; off > 0; off >>= 1)
        corr += __shfl_down_sync(0xFFFFFFFFu, corr, off);
    if (lane == 0) dpart[w] = corr;
    __syncthreads();

    if (t == 0) {
        double bsum = 0.0;
        #pragma unroll
        for (int i = 0; i < 16; i++) bsum += dpart[i];
        atomicAdd(&g_acc, bsum);
        __threadfence();
        unsigned ticket = atomicAdd(&g_done, 1u);
        if (ticket == BATCH - 1) {                   // last block: finalize + reset
            __threadfence();
            out[0] = (float)atomicAdd(&g_acc, 0.0);
            #pragma unroll 4
            for (int i = 0; i < BATCH; i++) {
                g_c2[i] = 0u; g_nc[i] = 0u; g_of[i] = 0u; g_eqcnt[i] = 0u;
            }
            g_acc = 0.0;
            __threadfence();
            g_done = 0u;
        }
    }
}

extern "C" void kernel_launch(void* const* d_in, const int* in_sizes, int n_in,
                              void* d_out, int out_size) {
    const float* scores = (const float*)d_in[0];   // [B, N, 2]
    const float* smap   = (const float*)d_in[1];   // [B, 1, H, W] == [B, N]
    const float* gumb   = (const float*)d_in[2];   // [B, N, 2]
    float* out = (float*)d_out;

    sweep_kernel<<<4096, 256>>>((const float4*)scores, (const uint4*)smap,
                                (const float4*)gumb);
    fix_kernel<<<BATCH, 512>>>((const float4*)scores, smap, (const float4*)gumb, out);
}

// round 15
// speedup vs baseline: 1.3575x; 1.3575x over previous
#include <cuda_runtime.h>
#include <cstdint>

#define BATCH 64
#define NTOK  65536            // 256*256
#define KSEL  16384
#define TOTAL (BATCH * NTOK)
#define CANDCAP 4096           // per-batch candidate capacity (global)
#define WCAP    64             // per-warp candidate capacity (expected ~10, +big margin)
#define MCAP    64             // boundary-bin member capacity (expected ~3)

// ---- device scratch (device globals; no allocations) ----
__device__ uint2    g_cand[BATCH * CANDCAP];  // (u bits, delta bits)
__device__ uint32_t g_nc[BATCH];     // candidate counts (zero-init; reset by finalize)
__device__ uint32_t g_c2[BATCH];     // counts >= P2     (zero-init; reset by finalize)
__device__ uint32_t g_of[BATCH];     // overflow flags   (zero-init; reset by finalize)
__device__ uint32_t g_eqcnt[BATCH];  // tie counter (fallback only; reset by finalize)
__device__ double   g_acc;           // loss accumulator
__device__ unsigned g_done;          // finalize ticket

#define P1F 0.73f
#define P2F 0.77f

// ============================================================================
// Kernel 1: THE sweep (83 MB), fully-coalesced unit layout.
// A "unit" = 2 tokens = one float4 of scores + one float4 of gumbel + one
// uint2 of smap. Thread handles 4 units u = base + j*256 + t: every LDG is
// lane-consecutive (128B/wavefront), unlike R10's 32B-strided pair loads.
// 2048 blocks x 256 thr (R10's proven shape). Same math/stash as R10.
// ============================================================================
__global__ __launch_bounds__(256) void sweep_kernel(const float4* __restrict__ zs4,
                                                    const uint2*  __restrict__ sm2,
                                                    const float4* __restrict__ gn4) {
    __shared__ uint2    wbuf[8 * WCAP];
    __shared__ uint32_t wcnt[8];
    __shared__ double   wpart[8];
    __shared__ uint32_t wc2[8];

    const int t    = threadIdx.x;
    const int lane = t & 31;
    const int w    = t >> 5;
    const int b    = blockIdx.x >> 5;               // 32 blocks per batch
    const int unitBase = blockIdx.x * 1024;         // units (2 tokens each)

    if (lane == 0) wcnt[w] = 0u;
    __syncwarp();

    const uint32_t P1 = __float_as_uint(P1F);
    const uint32_t P2 = __float_as_uint(P2F);
    const uint32_t W  = P2 - P1;

    float facc = 0.0f;
    uint32_t cnt2 = 0;

    #pragma unroll
    for (int j = 0; j < 4; j++) {
        const int u = unitBase + j * 256 + t;
        float4 z = __ldcs(&zs4[u]);
        float4 g = __ldcs(&gn4[u]);
        uint2  s = sm2[u];

        float d0 = (z.x + g.x) - (z.y + g.y);
        float d1 = (z.z + g.z) - (z.w + g.w);

        #pragma unroll
        for (int c = 0; c < 2; c++) {
            const float dd = (c == 0) ? d0 : d1;
            const uint32_t uv = (c == 0) ? s.x : s.y;
            const float cc = __logf(1.0f + __expf(-fabsf(dd)));
            const float sp = cc + fmaxf(dd, 0.0f);
            const float t_un = fminf(sp, 100.0f);
            const float t_se = fminf(sp - dd, 100.0f);
            const bool hi = (uv >= P2);
            cnt2 += hi;
            facc += hi ? t_se : t_un;
            if ((uv - P1) < W) {                    // rare (~4%): stash correction
                uint32_t idx = atomicAdd(&wcnt[w], 1u);
                if (idx < WCAP) wbuf[w * WCAP + idx] =
                    make_uint2(uv, __float_as_uint(t_se - t_un));
            }
        }
    }

    double acc = (double)facc;
    #pragma unroll
    for (int off = 16; off > 0; off >>= 1) {
        acc  += __shfl_down_sync(0xFFFFFFFFu, acc,  off);
        cnt2 += __shfl_down_sync(0xFFFFFFFFu, cnt2, off);
    }
    if (lane == 0) { wpart[w] = acc; wc2[w] = cnt2; }
    __syncwarp();

    // per-warp candidate flush (one global atomic per warp)
    uint32_t cw = wcnt[w];
    uint32_t n  = (cw > WCAP) ? WCAP : cw;
    uint32_t gbase = 0;
    if (lane == 0) {
        if (cw > WCAP) g_of[b] = 1u;
        gbase = atomicAdd(&g_nc[b], n);
        if (gbase + n > CANDCAP) g_of[b] = 1u;
    }
    gbase = __shfl_sync(0xFFFFFFFFu, gbase, 0);
    for (uint32_t i = lane; i < n; i += 32)
        if (gbase + i < CANDCAP) g_cand[b * CANDCAP + gbase + i] = wbuf[w * WCAP + i];

    __syncthreads();
    if (t == 0) {
        double bsum = 0.0; uint32_t tot2 = 0;
        #pragma unroll
        for (int i = 0; i < 8; i++) { bsum += wpart[i]; tot2 += wc2[i]; }
        atomicAdd(&g_acc, bsum);
        atomicAdd(&g_c2[b], tot2);
    }
}

// ============================================================================
// Kernel 2: per-batch correction (R10 version verbatim — measured-invariant).
// ============================================================================
__device__ __forceinline__ uint32_t suffix_excl_512(uint32_t v, uint32_t* wsum) {
    const int t = threadIdx.x, lane = t & 31, w = t >> 5;
    uint32_t s = v;
    #pragma unroll
    for (int off = 1; off < 32; off <<= 1) {
        uint32_t o = __shfl_down_sync(0xFFFFFFFFu, s, off);
        if (lane + off < 32) s += o;
    }
    if (lane == 0) wsum[w] = s;
    __syncthreads();
    if (t < 32) {
        uint32_t x  = (t < 16) ? wsum[t] : 0u;
        uint32_t sx = x;
        #pragma unroll
        for (int off = 1; off < 16; off <<= 1) {
            uint32_t o = __shfl_down_sync(0xFFFFFFFFu, sx, off);
            if (t + off < 16) sx += o;
        }
        if (t < 16) wsum[t] = sx - x;
    }
    __syncthreads();
    return wsum[w] + (s - v);
}

__global__ __launch_bounds__(512) void fix_kernel(const float4* __restrict__ zs4,
                                                  const float*  __restrict__ smap,
                                                  const float4* __restrict__ gn4,
                                                  float* __restrict__ out) {
    __shared__ uint2    scand[CANDCAP];     // 32 KB candidate stage
    __shared__ uint32_t hcnt[1024];
    __shared__ float    hsum[1024];
    __shared__ uint32_t wsum[32];
    __shared__ uint32_t sBin, sK, mcnt;
    __shared__ uint32_t mu[MCAP];
    __shared__ float    md[MCAP];
    __shared__ double   dpart[16];

    const int b = blockIdx.x;
    const int t = threadIdx.x;
    const int lane = t & 31;
    const int w    = t >> 5;
    const uint32_t P1 = __float_as_uint(P1F);
    const uint32_t P2 = __float_as_uint(P2F);

    const uint32_t nc = g_nc[b];
    const uint32_t c2 = g_c2[b];
    bool miss = (g_of[b] != 0u) || (c2 >= KSEL) || (c2 + nc < KSEL) || (nc > CANDCAP);

    const uint2* __restrict__ candg = g_cand + b * CANDCAP;
    const uint32_t* __restrict__ full =
        reinterpret_cast<const uint32_t*>(smap) + (size_t)b * NTOK;

    double corr = 0.0;

    if (!miss) {
        for (uint32_t i = t; i < nc; i += 512) scand[i] = __ldcg(&candg[i]);
        for (int i = t; i < 1024; i += 512) { hcnt[i] = 0u; hsum[i] = 0.0f; }
        if (t == 0) mcnt = 0u;
        __syncthreads();

        for (uint32_t i = t; i < nc; i += 512) {
            uint2 cv = scand[i];
            uint32_t bin = (cv.x - P1) >> 10;       // < 1024
            atomicAdd(&hcnt[bin], 1u);
            atomicAdd(&hsum[bin], __uint_as_float(cv.y));
        }
        __syncthreads();

        const uint32_t Kcur = (uint32_t)KSEL - c2;
        const int base = t * 2;
        uint32_t p = hcnt[base] + hcnt[base + 1];
        uint32_t sfx = suffix_excl_512(p, wsum);
        for (int j = 1; j >= 0; j--) {
            uint32_t h = hcnt[base + j];
            uint32_t s_incl = sfx + h;
            if (sfx < Kcur && s_incl >= Kcur) { sBin = (uint32_t)(base + j); sK = Kcur - sfx; }
            sfx = s_incl;
        }
        __syncthreads();
        const uint32_t bin = sBin;
        const uint32_t rk  = sK;

        float ch = 0.0f;
        for (int i = t; i < 1024; i += 512)
            if ((uint32_t)i > bin) ch += hsum[i];
        corr += (double)ch;

        for (uint32_t i = t; i < nc; i += 512) {
            uint2 cv = scand[i];
            if (((cv.x - P1) >> 10) == bin) {
                uint32_t idx = atomicAdd(&mcnt, 1u);
                if (idx < MCAP) { mu[idx] = cv.x; md[idx] = __uint_as_float(cv.y); }
            }
        }
        __syncthreads();

        if (mcnt <= MCAP) {
            if (w == 0) {
                const uint32_t m = mcnt;
                float csum = 0.0f;
                for (uint32_t e = lane; e < m; e += 32) {
                    uint32_t ue = mu[e];
                    uint32_t rank = 0;
                    for (uint32_t j = 0; j < m; j++) {
                        uint32_t uj = mu[j];
                        rank += (uj > ue) || (uj == ue && j < e);
                    }
                    if (rank < rk) csum += md[e];
                }
                #pragma unroll
                for (int off = 16; off > 0; off >>= 1)
                    csum += __shfl_down_sync(0xFFFFFFFFu, csum, off);
                if (lane == 0) corr += (double)csum;
            }
        } else {
            miss = true;
            corr = 0.0;
        }
        __syncthreads();
    }

    if (miss) {
        uint32_t Kcur = KSEL;
        uint32_t prefixVal = 0;
        for (int r = 0; r < 4; r++) {
            const int shift = 24 - 8 * r;
            if (t < 256) hcnt[t] = 0u;
            __syncthreads();
            for (int i = t; i < NTOK; i += 512) {
                uint32_t u = full[i];
                bool match = (r == 0) || ((u >> (shift + 8)) == prefixVal);
                if (match) atomicAdd(&hcnt[(u >> shift) & 255u], 1u);
            }
            __syncthreads();
            uint32_t p = (t < 256) ? hcnt[t] : 0u;
            uint32_t sfx = suffix_excl_512(p, wsum);
            if (t < 256) {
                uint32_t s_incl = sfx + p;
                if (sfx < Kcur && s_incl >= Kcur) { sBin = (uint32_t)t; sK = Kcur - sfx; }
            }
            __syncthreads();
            prefixVal = (prefixVal << 8) | sBin;
            Kcur = sK;
            __syncthreads();
        }
        const uint32_t T = prefixVal;
        const uint32_t req = sK;

        corr = 0.0;
        const float4* zsb = zs4 + (size_t)b * (NTOK / 2);
        const float4* gnb = gn4 + (size_t)b * (NTOK / 2);
        for (int i = t; i < NTOK / 2; i += 512) {       // 2 tokens per float4
            float4 z = zsb[i], g = gnb[i];
            float dv[2] = {(z.x + g.x) - (z.y + g.y), (z.z + g.z) - (z.w + g.w)};
            #pragma unroll
            for (int c = 0; c < 2; c++) {
                uint32_t u = full[2 * i + c];
                bool assumed = (u >= P2);
                bool truesel;
                if (u > T)       truesel = true;
                else if (u == T) truesel = (atomicAdd(&g_eqcnt[b], 1u) < req);
                else             truesel = false;
                if (truesel != assumed) {
                    float dd = dv[c];
                    float cc = __logf(1.0f + __expf(-fabsf(dd)));
                    float sp = cc + fmaxf(dd, 0.0f);
                    float delta = fminf(sp - dd, 100.0f) - fminf(sp, 100.0f);
                    corr += truesel ? (double)delta : -(double)delta;
                }
            }
        }
    }

    #pragma unroll
    for (int off = 16; off > 0; off >>= 1)
        corr += __shfl_down_sync(0xFFFFFFFFu, corr, off);
    if (lane == 0) dpart[w] = corr;
    __syncthreads();

    if (t == 0) {
        double bsum = 0.0;
        #pragma unroll
        for (int i = 0; i < 16; i++) bsum += dpart[i];
        atomicAdd(&g_acc, bsum);
        __threadfence();
        unsigned ticket = atomicAdd(&g_done, 1u);
        if (ticket == BATCH - 1) {                   // last block: finalize + reset
            __threadfence();
            out[0] = (float)atomicAdd(&g_acc, 0.0);
            #pragma unroll 4
            for (int i = 0; i < BATCH; i++) {
                g_c2[i] = 0u; g_nc[i] = 0u; g_of[i] = 0u; g_eqcnt[i] = 0u;
            }
            g_acc = 0.0;
            __threadfence();
            g_done = 0u;
        }
    }
}

extern "C" void kernel_launch(void* const* d_in, const int* in_sizes, int n_in,
                              void* d_out, int out_size) {
    const float* scores = (const float*)d_in[0];   // [B, N, 2]
    const float* smap   = (const float*)d_in[1];   // [B, 1, H, W] == [B, N]
    const float* gumb   = (const float*)d_in[2];   // [B, N, 2]
    float* out = (float*)d_out;

    sweep_kernel<<<2048, 256>>>((const float4*)scores, (const uint2*)smap,
                                (const float4*)gumb);
    fix_kernel<<<BATCH, 512>>>((const float4*)scores, smap, (const float4*)gumb, out);
}